// round 13
// baseline (speedup 1.0000x reference)
#include <cuda_runtime.h>
#include <cstdint>

#define NTHR 288                 // 8 consumer warps (256 thr) + 1 producer warp
#define NCONS 256
#define NSTAGES 4
#define STAGE_ELEMS 1024                  // elements per tensor per stage
#define STAGE_BYTES (STAGE_ELEMS * 4)     // 4 KB per tensor per stage
#define MAXBLK 2048

// Per-block partials, SoA: g_partials[c*MAXBLK + block], c in 0..11
// [0..3]=count(pred==c) [4..7]=count(label==c) [8..11]=count(pred==label==c)
__device__ unsigned int g_partials[12 * MAXBLK];
__device__ unsigned int g_ticket;   // zero-init at load; reset by last block each run

// ---------------- mbarrier / bulk-copy helpers ----------------
#define MB_INIT(addr, cnt) \
    asm volatile("mbarrier.init.shared.b64 [%0], %1;" :: "r"(addr), "r"(cnt) : "memory")
#define MB_EXPECT_TX(addr, tx) \
    asm volatile("mbarrier.arrive.expect_tx.shared.b64 _, [%0], %1;" :: "r"(addr), "r"(tx) : "memory")
#define MB_ARRIVE(addr) \
    asm volatile("mbarrier.arrive.shared.b64 _, [%0];" :: "r"(addr) : "memory")
#define MB_WAIT(addr, ph) do {                                                   \
    unsigned int _done;                                                          \
    asm volatile("{\n\t.reg .pred p;\n\t"                                        \
        "mbarrier.try_wait.parity.acquire.cta.shared::cta.b64 p, [%1], %2;\n\t"  \
        "selp.b32 %0, 1, 0, p;\n\t}"                                             \
        : "=r"(_done) : "r"(addr), "r"(ph) : "memory");                          \
    while (!_done) {                                                             \
        asm volatile("{\n\t.reg .pred p;\n\t"                                    \
            "mbarrier.try_wait.parity.acquire.cta.shared::cta.b64 p, [%1], %2, 0x989680;\n\t" \
            "selp.b32 %0, 1, 0, p;\n\t}"                                         \
            : "=r"(_done) : "r"(addr), "r"(ph) : "memory");                      \
    }                                                                            \
} while (0)
#define BULK_G2S(dst, src, bytes, bar) \
    asm volatile("cp.async.bulk.shared::cluster.global.mbarrier::complete_tx::bytes " \
                 "[%0], [%1], %2, [%3];"                                          \
                 :: "r"(dst), "l"(src), "r"(bytes), "r"(bar) : "memory")

__device__ __forceinline__ unsigned int smem_u32(const void* p) {
    return (unsigned int)__cvta_generic_to_shared(p);
}

__global__ __launch_bounds__(NTHR, 6) void iou_ws_kernel(
    const float* __restrict__ preds,
    const int*   __restrict__ labels,
    long long n,
    float* __restrict__ out)
{
    __shared__ __align__(128) unsigned char sm_pred[NSTAGES][STAGE_BYTES];
    __shared__ __align__(128) unsigned char sm_lab [NSTAGES][STAGE_BYTES];
    __shared__ __align__(8) unsigned long long mb_full [NSTAGES];
    __shared__ __align__(8) unsigned long long mb_empty[NSTAGES];
    __shared__ unsigned int s[12];
    __shared__ bool s_last;

    const int tid = threadIdx.x;
    const unsigned int G = gridDim.x;
    const long long total_stages = n / STAGE_ELEMS;

    if (tid == 0) {
        #pragma unroll
        for (int i = 0; i < NSTAGES; i++) {
            MB_INIT(smem_u32(&mb_full[i]),  1u);   // tx-based completion
            MB_INIT(smem_u32(&mb_empty[i]), 8u);   // one arrive per consumer warp
        }
        asm volatile("fence.proxy.async.shared::cta;" ::: "memory");
    }
    if (tid < 12) s[tid] = 0u;
    __syncthreads();

    // Full-width counters (flushed rarely) + packed 8-bit accumulators.
    unsigned int fp[4] = {0u,0u,0u,0u};
    unsigned int fl[4] = {0u,0u,0u,0u};
    unsigned int fe[4] = {0u,0u,0u,0u};
    unsigned int ap = 0u, al = 0u, ae = 0u;
    int pend = 0;

#define FLUSH_PACKED() do {                                   \
        _Pragma("unroll")                                     \
        for (int c = 0; c < 4; c++) {                         \
            fp[c] += (ap >> (8*c)) & 0xFFu;                   \
            fl[c] += (al >> (8*c)) & 0xFFu;                   \
            fe[c] += (ae >> (8*c)) & 0xFFu;                   \
        }                                                     \
        ap = 0u; al = 0u; ae = 0u; pend = 0;                  \
    } while (0)

    if (tid == NCONS) {
        // ================= PRODUCER (single thread, warp 8) =================
        // Runs ahead of consumers, gated only by empty barriers.
        // Phase starts at 1: first NSTAGES waits pass immediately (fresh barriers).
        int slot = 0, phase = 1;
        for (long long k = 0; ; k++) {
            long long st = (long long)blockIdx.x + k * G;
            if (st >= total_stages) break;

            MB_WAIT(smem_u32(&mb_empty[slot]), (unsigned int)phase);

            unsigned int bar = smem_u32(&mb_full[slot]);
            MB_EXPECT_TX(bar, 2u * STAGE_BYTES);
            BULK_G2S(smem_u32(&sm_pred[slot][0]), preds  + st * STAGE_ELEMS,
                     (unsigned int)STAGE_BYTES, bar);
            BULK_G2S(smem_u32(&sm_lab[slot][0]),  labels + st * STAGE_ELEMS,
                     (unsigned int)STAGE_BYTES, bar);

            if (++slot == NSTAGES) { slot = 0; phase ^= 1; }
        }
    } else if (tid < NCONS) {
        // ================= CONSUMERS (8 warps, 256 threads) =================
        int slot = 0, phase = 0;
        for (long long k = 0; ; k++) {
            long long st = (long long)blockIdx.x + k * G;
            if (st >= total_stages) break;

            MB_WAIT(smem_u32(&mb_full[slot]), (unsigned int)phase);

            const float4* pp = (const float4*)&sm_pred[slot][0];
            const int4*   ll = (const int4*)&sm_lab[slot][0];
            float4 pv = pp[tid];     // 256 threads x 16B = 4 KB stage
            int4   lv = ll[tid];

            // magic-number float->int: bits(x + 1.5*2^23) & 3  (x in 0..3)
            int p0 = (int)(__float_as_uint(pv.x + 12582912.0f) & 3u);
            int p1 = (int)(__float_as_uint(pv.y + 12582912.0f) & 3u);
            int p2 = (int)(__float_as_uint(pv.z + 12582912.0f) & 3u);
            int p3 = (int)(__float_as_uint(pv.w + 12582912.0f) & 3u);
            ap += (1u << (p0 << 3)) + (1u << (p1 << 3))
                + (1u << (p2 << 3)) + (1u << (p3 << 3));
            al += (1u << (lv.x << 3)) + (1u << (lv.y << 3))
                + (1u << (lv.z << 3)) + (1u << (lv.w << 3));
            ae += (p0 == lv.x ? (1u << (p0 << 3)) : 0u)
                + (p1 == lv.y ? (1u << (p1 << 3)) : 0u)
                + (p2 == lv.z ? (1u << (p2 << 3)) : 0u)
                + (p3 == lv.w ? (1u << (p3 << 3)) : 0u);

            if (++pend >= 60) FLUSH_PACKED();   // max 60*4=240 < 255

            // All lanes have consumed their smem data (values live in regs
            // feeding the adds above); one arrival per warp frees the slot.
            __syncwarp();
            if ((tid & 31) == 0) MB_ARRIVE(smem_u32(&mb_empty[slot]));

            if (++slot == NSTAGES) { slot = 0; phase ^= 1; }
        }
    }
    FLUSH_PACKED();

    // ---- Scalar tail (elements beyond full stages), consumers only ----
    if (tid < NCONS) {
        for (long long j = total_stages * STAGE_ELEMS + (long long)blockIdx.x * NCONS + tid;
             j < n; j += (long long)G * NCONS) {
            int p = (int)preds[j];
            int l = labels[j];
            ap += 1u << (p << 3);
            al += 1u << (l << 3);
            ae += (p == l) ? (1u << (p << 3)) : 0u;
            if (++pend >= 60) FLUSH_PACKED();
        }
    }
    FLUSH_PACKED();
#undef FLUSH_PACKED

    // ---- Warp reduction via REDUX (producer warp contributes zeros) ----
    #pragma unroll
    for (int c = 0; c < 4; c++) {
        fp[c] = __reduce_add_sync(0xFFFFFFFFu, fp[c]);
        fl[c] = __reduce_add_sync(0xFFFFFFFFu, fl[c]);
        fe[c] = __reduce_add_sync(0xFFFFFFFFu, fe[c]);
    }

    __syncthreads();
    if ((tid & 31) == 0) {
        #pragma unroll
        for (int c = 0; c < 4; c++) {
            atomicAdd(&s[c],     fp[c]);
            atomicAdd(&s[4 + c], fl[c]);
            atomicAdd(&s[8 + c], fe[c]);
        }
    }
    __syncthreads();

    if (tid < 12)
        g_partials[tid * MAXBLK + blockIdx.x] = s[tid];

    __threadfence();
    __syncthreads();

    if (tid == 0) {
        unsigned int old = atomicAdd(&g_ticket, 1u);
        s_last = (old == gridDim.x - 1u);
    }
    __syncthreads();

    if (s_last) {
        unsigned int loc[12];
        #pragma unroll
        for (int c = 0; c < 12; c++) loc[c] = 0u;

        for (unsigned int j = tid; j < gridDim.x; j += NTHR) {
            #pragma unroll
            for (int c = 0; c < 12; c++)
                loc[c] += __ldcg(&g_partials[c * MAXBLK + j]);
        }
        #pragma unroll
        for (int c = 0; c < 12; c++)
            loc[c] = __reduce_add_sync(0xFFFFFFFFu, loc[c]);

        __shared__ unsigned int s_tot[12];
        if (tid < 12) s_tot[tid] = 0u;
        __syncthreads();
        if ((tid & 31) == 0) {
            #pragma unroll
            for (int c = 0; c < 12; c++) atomicAdd(&s_tot[c], loc[c]);
        }
        __syncthreads();

        if (tid < 4) {
            int c = tid;
            float inter = (float)s_tot[8 + c];
            float uni   = (float)s_tot[c] + (float)s_tot[4 + c] - inter;
            float iou   = (uni == 0.0f) ? 1.0f : (inter / uni);
            out[c] = 1.0f - 100.0f * iou;
        }
        if (tid == 0)
            atomicExch(&g_ticket, 0u);   // reset for next graph replay
    }
}

extern "C" void kernel_launch(void* const* d_in, const int* in_sizes, int n_in,
                              void* d_out, int out_size)
{
    const float* preds  = (const float*)d_in[0];
    const int*   labels = (const int*)d_in[1];
    float*       out    = (float*)d_out;

    long long n = (long long)in_sizes[0];

    static int nsm = 0;
    if (nsm == 0) {
        int dev = 0;
        cudaGetDevice(&dev);
        cudaDeviceGetAttribute(&nsm, cudaDevAttrMultiProcessorCount, dev);
        if (nsm <= 0) nsm = 148;
    }
    int nblk = 6 * nsm;          // single wave at 6 CTAs/SM (~33 KB smem each)
    if (nblk > MAXBLK) nblk = MAXBLK;

    iou_ws_kernel<<<nblk, NTHR>>>(preds, labels, n, out);
}

// round 14
// speedup vs baseline: 1.0626x; 1.0626x over previous
#include <cuda_runtime.h>
#include <cstdint>

#define NTHR 256
#define NSTAGES 3
#define STAGE_ELEMS 2048                  // elements per tensor per stage
#define STAGE_BYTES (STAGE_ELEMS * 4)     // 8 KB per tensor per stage
#define VPT (STAGE_ELEMS / 4 / NTHR)      // 2 float4 per thread per stage
#define MAXBLK 2048

// Per-block partials, SoA: g_partials[c*MAXBLK + block], c in 0..11
// [0..3]=count(pred==c) [4..7]=count(label==c) [8..11]=count(pred==label==c)
__device__ unsigned int g_partials[12 * MAXBLK];
__device__ unsigned int g_ticket;   // zero-init at load; reset by last block each run

// ---------------- mbarrier / bulk-copy helpers ----------------
#define MB_INIT(addr, cnt) \
    asm volatile("mbarrier.init.shared.b64 [%0], %1;" :: "r"(addr), "r"(cnt) : "memory")
#define MB_EXPECT_TX(addr, tx) \
    asm volatile("mbarrier.arrive.expect_tx.shared.b64 _, [%0], %1;" :: "r"(addr), "r"(tx) : "memory")
#define MB_ARRIVE(addr) \
    asm volatile("mbarrier.arrive.shared.b64 _, [%0];" :: "r"(addr) : "memory")
#define MB_WAIT(addr, ph) do {                                                   \
    unsigned int _done;                                                          \
    asm volatile("{\n\t.reg .pred p;\n\t"                                        \
        "mbarrier.try_wait.parity.acquire.cta.shared::cta.b64 p, [%1], %2;\n\t"  \
        "selp.b32 %0, 1, 0, p;\n\t}"                                             \
        : "=r"(_done) : "r"(addr), "r"(ph) : "memory");                          \
    while (!_done) {                                                             \
        asm volatile("{\n\t.reg .pred p;\n\t"                                    \
            "mbarrier.try_wait.parity.acquire.cta.shared::cta.b64 p, [%1], %2, 0x989680;\n\t" \
            "selp.b32 %0, 1, 0, p;\n\t}"                                         \
            : "=r"(_done) : "r"(addr), "r"(ph) : "memory");                      \
    }                                                                            \
} while (0)
#define BULK_G2S(dst, src, bytes, bar) \
    asm volatile("cp.async.bulk.shared::cluster.global.mbarrier::complete_tx::bytes " \
                 "[%0], [%1], %2, [%3];"                                          \
                 :: "r"(dst), "l"(src), "r"(bytes), "r"(bar) : "memory")

__device__ __forceinline__ unsigned int smem_u32(const void* p) {
    return (unsigned int)__cvta_generic_to_shared(p);
}

// count one vec4 pair into packed accumulators
#define COUNT_PAIR(pv, lv) do {                                                  \
    int p0 = (int)(__float_as_uint((pv).x + 12582912.0f) & 3u);                  \
    int p1 = (int)(__float_as_uint((pv).y + 12582912.0f) & 3u);                  \
    int p2 = (int)(__float_as_uint((pv).z + 12582912.0f) & 3u);                  \
    int p3 = (int)(__float_as_uint((pv).w + 12582912.0f) & 3u);                  \
    ap += (1u << (p0 << 3)) + (1u << (p1 << 3))                                  \
        + (1u << (p2 << 3)) + (1u << (p3 << 3));                                 \
    al += (1u << ((lv).x << 3)) + (1u << ((lv).y << 3))                          \
        + (1u << ((lv).z << 3)) + (1u << ((lv).w << 3));                         \
    ae += (p0 == (lv).x ? (1u << (p0 << 3)) : 0u)                                \
        + (p1 == (lv).y ? (1u << (p1 << 3)) : 0u)                                \
        + (p2 == (lv).z ? (1u << (p2 << 3)) : 0u)                                \
        + (p3 == (lv).w ? (1u << (p3 << 3)) : 0u);                               \
} while (0)

__global__ __launch_bounds__(NTHR, 4) void iou_hybrid_kernel(
    const float* __restrict__ preds,
    const int*   __restrict__ labels,
    long long n,
    float* __restrict__ out)
{
    __shared__ __align__(128) unsigned char sm_pred[NSTAGES][STAGE_BYTES];
    __shared__ __align__(128) unsigned char sm_lab [NSTAGES][STAGE_BYTES];
    __shared__ __align__(8) unsigned long long mb_full [NSTAGES];
    __shared__ __align__(8) unsigned long long mb_empty[NSTAGES];
    __shared__ unsigned int s[12];
    __shared__ bool s_last;

    const int tid = threadIdx.x;
    const unsigned int G = gridDim.x;

    // ---- Region split: first half via bulk-copy ring, second half via LDG ----
    const long long bulk_stages = (n / 2) / STAGE_ELEMS;
    const long long bulk_elems  = bulk_stages * STAGE_ELEMS;     // 16B-aligned offset
    const float4* predL4 = (const float4*)(preds  + bulk_elems);
    const int4*   labL4  = (const int4*)  (labels + bulk_elems);
    const long long nL4  = (n - bulk_elems) >> 2;
    const long long strideL = (long long)G * NTHR;

    if (tid == 0) {
        #pragma unroll
        for (int i = 0; i < NSTAGES; i++) {
            MB_INIT(smem_u32(&mb_full[i]),  1u);              // tx-based
            MB_INIT(smem_u32(&mb_empty[i]), NTHR / 32);       // per-warp arrivals
        }
        asm volatile("fence.proxy.async.shared::cta;" ::: "memory");
    }
    if (tid < 12) s[tid] = 0u;
    __syncthreads();

    // ---- Prologue: prime all stages ----
    if (tid == 0) {
        #pragma unroll
        for (int j = 0; j < NSTAGES; j++) {
            long long st = (long long)blockIdx.x + (long long)j * G;
            if (st < bulk_stages) {
                unsigned int bar = smem_u32(&mb_full[j]);
                MB_EXPECT_TX(bar, 2u * STAGE_BYTES);
                BULK_G2S(smem_u32(&sm_pred[j][0]), preds  + st * STAGE_ELEMS,
                         (unsigned int)STAGE_BYTES, bar);
                BULK_G2S(smem_u32(&sm_lab[j][0]),  labels + st * STAGE_ELEMS,
                         (unsigned int)STAGE_BYTES, bar);
            }
        }
    }

    unsigned int fp[4] = {0u,0u,0u,0u};
    unsigned int fl[4] = {0u,0u,0u,0u};
    unsigned int fe[4] = {0u,0u,0u,0u};
    unsigned int ap = 0u, al = 0u, ae = 0u;
    int pend = 0;

#define FLUSH_PACKED() do {                                   \
        _Pragma("unroll")                                     \
        for (int c = 0; c < 4; c++) {                         \
            fp[c] += (ap >> (8*c)) & 0xFFu;                   \
            fl[c] += (al >> (8*c)) & 0xFFu;                   \
            fe[c] += (ae >> (8*c)) & 0xFFu;                   \
        }                                                     \
        ap = 0u; al = 0u; ae = 0u; pend = 0;                  \
    } while (0)

    // ---- Hybrid mainloop: one smem stage + one LDG batch per iteration ----
    {
        long long iL = (long long)blockIdx.x * NTHR + tid;   // vec4 idx in LDG region
        int slot = 0, phase = 0;
        for (long long k = 0; ; k++) {
            long long st = (long long)blockIdx.x + k * G;
            bool have_stage = (st < bulk_stages);            // uniform across CTA
            bool have_ldg   = (iL < nL4);                    // per-thread
            if (!have_stage && !have_ldg) break;

            // (1) Issue the LDG batch FIRST — flight time hides behind smem work.
            float4 pv[4]; int4 lv[4]; int nb = 0;
            if (have_ldg) {
                if (iL + 3 * strideL < nL4) {
                    #pragma unroll
                    for (int u = 0; u < 4; u++) pv[u] = __ldcg(&predL4[iL + u * strideL]);
                    #pragma unroll
                    for (int u = 0; u < 4; u++) lv[u] = __ldcg(&labL4[iL + u * strideL]);
                    nb = 4;
                } else {
                    #pragma unroll
                    for (int u = 0; u < 4; u++) {
                        if (iL + u * strideL < nL4) {
                            pv[u] = __ldcg(&predL4[iL + u * strideL]);
                            lv[u] = __ldcg(&labL4 [iL + u * strideL]);
                            nb = u + 1;
                        }
                    }
                }
                iL += 4 * strideL;
            }

            // (2) Consume the smem stage while LDGs are in flight.
            if (have_stage) {
                MB_WAIT(smem_u32(&mb_full[slot]), (unsigned int)phase);
                const float4* pp = (const float4*)&sm_pred[slot][0];
                const int4*   ll = (const int4*)&sm_lab[slot][0];
                #pragma unroll
                for (int v = 0; v < VPT; v++) {
                    float4 spv = pp[v * NTHR + tid];
                    int4   slv = ll[v * NTHR + tid];
                    COUNT_PAIR(spv, slv);
                }
                __syncwarp();
                if ((tid & 31) == 0) MB_ARRIVE(smem_u32(&mb_empty[slot]));
            }

            // (3) Consume the LDG batch (predicated unroll keeps regs, no local mem).
            #pragma unroll
            for (int u = 0; u < 4; u++)
                if (u < nb) COUNT_PAIR(pv[u], lv[u]);

            pend += VPT + 4;
            if (pend >= 56) FLUSH_PACKED();   // max 60 vec4 * 4 = 240 < 255

            // (4) Refill this slot for stage st + NSTAGES*G.
            if (have_stage) {
                if (tid == 0) {
                    long long nst = st + (long long)NSTAGES * G;
                    if (nst < bulk_stages) {
                        MB_WAIT(smem_u32(&mb_empty[slot]), (unsigned int)phase);
                        unsigned int bar = smem_u32(&mb_full[slot]);
                        MB_EXPECT_TX(bar, 2u * STAGE_BYTES);
                        BULK_G2S(smem_u32(&sm_pred[slot][0]), preds  + nst * STAGE_ELEMS,
                                 (unsigned int)STAGE_BYTES, bar);
                        BULK_G2S(smem_u32(&sm_lab[slot][0]),  labels + nst * STAGE_ELEMS,
                                 (unsigned int)STAGE_BYTES, bar);
                    }
                }
                if (++slot == NSTAGES) { slot = 0; phase ^= 1; }
            }
        }
    }
    FLUSH_PACKED();

    // ---- Scalar tail (n not multiple of 4) ----
    for (long long j = bulk_elems + nL4 * 4 + (long long)blockIdx.x * NTHR + tid;
         j < n; j += strideL) {
        int p = (int)preds[j];
        int l = labels[j];
        ap += 1u << (p << 3);
        al += 1u << (l << 3);
        ae += (p == l) ? (1u << (p << 3)) : 0u;
        if (++pend >= 56) FLUSH_PACKED();
    }
    FLUSH_PACKED();
#undef FLUSH_PACKED

    // ---- Warp reduction via REDUX ----
    #pragma unroll
    for (int c = 0; c < 4; c++) {
        fp[c] = __reduce_add_sync(0xFFFFFFFFu, fp[c]);
        fl[c] = __reduce_add_sync(0xFFFFFFFFu, fl[c]);
        fe[c] = __reduce_add_sync(0xFFFFFFFFu, fe[c]);
    }

    __syncthreads();
    if ((tid & 31) == 0) {
        #pragma unroll
        for (int c = 0; c < 4; c++) {
            atomicAdd(&s[c],     fp[c]);
            atomicAdd(&s[4 + c], fl[c]);
            atomicAdd(&s[8 + c], fe[c]);
        }
    }
    __syncthreads();

    if (tid < 12)
        g_partials[tid * MAXBLK + blockIdx.x] = s[tid];

    __threadfence();
    __syncthreads();

    if (tid == 0) {
        unsigned int old = atomicAdd(&g_ticket, 1u);
        s_last = (old == gridDim.x - 1u);
    }
    __syncthreads();

    if (s_last) {
        unsigned int loc[12];
        #pragma unroll
        for (int c = 0; c < 12; c++) loc[c] = 0u;

        for (unsigned int j = tid; j < gridDim.x; j += NTHR) {
            #pragma unroll
            for (int c = 0; c < 12; c++)
                loc[c] += __ldcg(&g_partials[c * MAXBLK + j]);
        }
        #pragma unroll
        for (int c = 0; c < 12; c++)
            loc[c] = __reduce_add_sync(0xFFFFFFFFu, loc[c]);

        __shared__ unsigned int s_tot[12];
        if (tid < 12) s_tot[tid] = 0u;
        __syncthreads();
        if ((tid & 31) == 0) {
            #pragma unroll
            for (int c = 0; c < 12; c++) atomicAdd(&s_tot[c], loc[c]);
        }
        __syncthreads();

        if (tid < 4) {
            int c = tid;
            float inter = (float)s_tot[8 + c];
            float uni   = (float)s_tot[c] + (float)s_tot[4 + c] - inter;
            float iou   = (uni == 0.0f) ? 1.0f : (inter / uni);
            out[c] = 1.0f - 100.0f * iou;
        }
        if (tid == 0)
            atomicExch(&g_ticket, 0u);   // reset for next graph replay
    }
}

extern "C" void kernel_launch(void* const* d_in, const int* in_sizes, int n_in,
                              void* d_out, int out_size)
{
    const float* preds  = (const float*)d_in[0];
    const int*   labels = (const int*)d_in[1];
    float*       out    = (float*)d_out;

    long long n = (long long)in_sizes[0];

    static int nsm = 0;
    if (nsm == 0) {
        int dev = 0;
        cudaGetDevice(&dev);
        cudaDeviceGetAttribute(&nsm, cudaDevAttrMultiProcessorCount, dev);
        if (nsm <= 0) nsm = 148;
    }
    int nblk = 4 * nsm;          // single wave at 4 CTAs/SM (~49 KB smem each)
    if (nblk > MAXBLK) nblk = MAXBLK;

    iou_hybrid_kernel<<<nblk, NTHR>>>(preds, labels, n, out);
}